// round 1
// baseline (speedup 1.0000x reference)
#include <cuda_runtime.h>

#define NN 50000
#define EE 800000
#define DM 128
#define RD 32
#define KIN 160          // IN_DIM + LABEL_DIM
#define LN_EPS 1e-5f

// ---------------- scratch (device globals; no allocation allowed) -----------
__device__ float g_h[NN * DM];     // h after input proj / layer outputs (ping)
__device__ float g_h2[NN * DM];    // pong
__device__ float g_aggH[NN * DM];  // sum of h[src] per dst
__device__ float g_aggR[NN * RD];  // sum of rel_emb[edge_rel] per dst
__device__ float g_inv[NN];        // deg accumulator, then 1/deg

// ---------------- helpers ----------------------------------------------------
__device__ __forceinline__ void red_add_v4(float* addr, float4 v) {
    asm volatile("red.global.add.v4.f32 [%0], {%1,%2,%3,%4};"
                 :: "l"(addr), "f"(v.x), "f"(v.y), "f"(v.z), "f"(v.w)
                 : "memory");
}

__global__ void k_zero(float* __restrict__ p, int n) {
    int i = blockIdx.x * blockDim.x + threadIdx.x;
    int stride = gridDim.x * blockDim.x;
    for (; i < n; i += stride) p[i] = 0.f;
}

__global__ void k_deg(const int* __restrict__ dst) {
    int i = blockIdx.x * blockDim.x + threadIdx.x;
    if (i < EE) atomicAdd(&g_inv[dst[i]], 1.0f);
}

__global__ void k_invdeg() {
    int i = blockIdx.x * blockDim.x + threadIdx.x;
    if (i < NN) {
        float d = g_inv[i];
        g_inv[i] = d > 0.f ? (1.f / d) : 0.f;
    }
}

// ---------------- input projection: h = relu([x, label_emb[label]] @ W + b) --
extern __shared__ float smdyn[];

__global__ __launch_bounds__(256) void k_input(
    const float* __restrict__ x, const int* __restrict__ label,
    const float* __restrict__ lemb, const float* __restrict__ W,
    const float* __restrict__ b, float* __restrict__ hout)
{
    float* Ws = smdyn;             // KIN*DM
    float* bs = Ws + KIN * DM;     // DM
    float* ins = bs + DM;          // 8 * KIN
    int tid = threadIdx.x;

    for (int i = tid; i < (KIN * DM) / 4; i += 256)
        ((float4*)Ws)[i] = ((const float4*)W)[i];
    for (int i = tid; i < DM; i += 256) bs[i] = b[i];
    __syncthreads();

    int w = tid >> 5, lane = tid & 31;
    for (int base = blockIdx.x * 8; base < NN; base += gridDim.x * 8) {
        int v = base + w;
        if (v < NN) {
            float* in = ins + w * KIN;
            ((float4*)in)[lane] = ((const float4*)(x + (size_t)v * DM))[lane];
            int lb = label[v];
            in[DM + lane] = lemb[lb * 32 + lane];
            __syncwarp();

            int c = lane * 4;
            float4 acc = *(float4*)(bs + c);
            #pragma unroll 8
            for (int k = 0; k < KIN; k++) {
                float s = in[k];
                float4 wv = *(float4*)(Ws + k * DM + c);
                acc.x += s * wv.x; acc.y += s * wv.y;
                acc.z += s * wv.z; acc.w += s * wv.w;
            }
            acc.x = fmaxf(acc.x, 0.f); acc.y = fmaxf(acc.y, 0.f);
            acc.z = fmaxf(acc.z, 0.f); acc.w = fmaxf(acc.w, 0.f);
            ((float4*)(hout + (size_t)v * DM))[lane] = acc;
        }
    }
}

// ---------------- edge pass: aggH[dst] += h[src]; aggR[dst] += rel[edge_rel] -
__global__ __launch_bounds__(256) void k_edge(
    const int* __restrict__ src, const int* __restrict__ dst,
    const int* __restrict__ erel, const float* __restrict__ h,
    const float* __restrict__ rel)
{
    int warp = (blockIdx.x * blockDim.x + threadIdx.x) >> 5;
    int lane = threadIdx.x & 31;
    if (warp >= EE) return;

    int s = __ldg(&src[warp]);
    int d = __ldg(&dst[warp]);

    float4 hv = ((const float4*)(h + (size_t)s * DM))[lane];
    red_add_v4(&g_aggH[(size_t)d * DM + lane * 4], hv);

    if (lane < 8) {
        int r = __ldg(&erel[warp]);
        float4 rv = ((const float4*)(rel + (size_t)r * RD))[lane];
        red_add_v4(&g_aggR[(size_t)d * RD + lane * 4], rv);
    }
}

// ---------------- node pass: fused 3-GEMM + bias + relu + layernorm ----------
__global__ __launch_bounds__(256) void k_node(
    const float* __restrict__ hin,
    const float* __restrict__ Wself, const float* __restrict__ Wn,
    const float* __restrict__ Wr, const float* __restrict__ bias,
    const float* __restrict__ lng, const float* __restrict__ lnb,
    float* __restrict__ hout)
{
    float* Ws  = smdyn;                 // DM*DM
    float* Wns = Ws + DM * DM;          // DM*DM
    float* Wrs = Wns + DM * DM;         // RD*DM
    float* bs  = Wrs + RD * DM;         // DM
    float* gs  = bs + DM;               // DM
    float* lbs = gs + DM;               // DM
    float* ins = lbs + DM;              // 8 * 288

    int tid = threadIdx.x;
    for (int i = tid; i < (DM * DM) / 4; i += 256) {
        ((float4*)Ws)[i]  = ((const float4*)Wself)[i];
        ((float4*)Wns)[i] = ((const float4*)Wn)[i];
    }
    for (int i = tid; i < (RD * DM) / 4; i += 256)
        ((float4*)Wrs)[i] = ((const float4*)Wr)[i];
    for (int i = tid; i < DM; i += 256) {
        bs[i] = bias[i]; gs[i] = lng[i]; lbs[i] = lnb[i];
    }
    __syncthreads();

    int w = tid >> 5, lane = tid & 31;
    for (int base = blockIdx.x * 8; base < NN; base += gridDim.x * 8) {
        int v = base + w;
        if (v < NN) {
            float iv = g_inv[v];
            float* in = ins + w * 288;

            ((float4*)in)[lane] = ((const float4*)(hin + (size_t)v * DM))[lane];
            float4 av = ((const float4*)(g_aggH + (size_t)v * DM))[lane];
            av.x *= iv; av.y *= iv; av.z *= iv; av.w *= iv;
            ((float4*)(in + DM))[lane] = av;
            if (lane < 8) {
                float4 rv = ((const float4*)(g_aggR + (size_t)v * RD))[lane];
                rv.x *= iv; rv.y *= iv; rv.z *= iv; rv.w *= iv;
                ((float4*)(in + 2 * DM))[lane] = rv;
            }
            __syncwarp();

            int c = lane * 4;
            float4 acc = *(float4*)(bs + c);
            #pragma unroll 8
            for (int k = 0; k < DM; k++) {
                float s = in[k];
                float4 wv = *(float4*)(Ws + k * DM + c);
                acc.x += s * wv.x; acc.y += s * wv.y;
                acc.z += s * wv.z; acc.w += s * wv.w;
            }
            #pragma unroll 8
            for (int k = 0; k < DM; k++) {
                float s = in[DM + k];
                float4 wv = *(float4*)(Wns + k * DM + c);
                acc.x += s * wv.x; acc.y += s * wv.y;
                acc.z += s * wv.z; acc.w += s * wv.w;
            }
            #pragma unroll 8
            for (int k = 0; k < RD; k++) {
                float s = in[2 * DM + k];
                float4 wv = *(float4*)(Wrs + k * DM + c);
                acc.x += s * wv.x; acc.y += s * wv.y;
                acc.z += s * wv.z; acc.w += s * wv.w;
            }
            // relu
            acc.x = fmaxf(acc.x, 0.f); acc.y = fmaxf(acc.y, 0.f);
            acc.z = fmaxf(acc.z, 0.f); acc.w = fmaxf(acc.w, 0.f);

            // layernorm over 128 (warp reduce, 4 vals/lane)
            float s1 = acc.x + acc.y + acc.z + acc.w;
            float s2 = acc.x * acc.x + acc.y * acc.y + acc.z * acc.z + acc.w * acc.w;
            #pragma unroll
            for (int o = 16; o > 0; o >>= 1) {
                s1 += __shfl_xor_sync(0xffffffffu, s1, o);
                s2 += __shfl_xor_sync(0xffffffffu, s2, o);
            }
            float mu  = s1 * (1.f / 128.f);
            float var = s2 * (1.f / 128.f) - mu * mu;
            float rs  = rsqrtf(var + LN_EPS);

            float4 o4;
            o4.x = (acc.x - mu) * rs * gs[c + 0] + lbs[c + 0];
            o4.y = (acc.y - mu) * rs * gs[c + 1] + lbs[c + 1];
            o4.z = (acc.z - mu) * rs * gs[c + 2] + lbs[c + 2];
            o4.w = (acc.w - mu) * rs * gs[c + 3] + lbs[c + 3];
            ((float4*)(hout + (size_t)v * DM))[lane] = o4;
        }
    }
}

// ---------------- host launch -------------------------------------------------
extern "C" void kernel_launch(void* const* d_in, const int* in_sizes, int n_in,
                              void* d_out, int out_size)
{
    const float* x      = (const float*)d_in[0];
    const int*   label  = (const int*)d_in[1];
    const int*   eidx   = (const int*)d_in[2];   // [2, E]: row0 src, row1 dst
    const int*   erel   = (const int*)d_in[3];
    const float* lemb   = (const float*)d_in[4];
    const float* Win    = (const float*)d_in[5];
    const float* bin    = (const float*)d_in[6];
    const float* relemb = (const float*)d_in[7]; // [2,1024,32]
    const float* Wn     = (const float*)d_in[8];  // lin_neigh_w [2,128,128]
    const float* Wself  = (const float*)d_in[9];  // lin_self_w  [2,128,128]
    const float* bself  = (const float*)d_in[10]; // [2,128]
    const float* Wr     = (const float*)d_in[11]; // lin_rel_w [2,32,128]
    const float* lng    = (const float*)d_in[12];
    const float* lnb    = (const float*)d_in[13];
    float* out = (float*)d_out;

    float *p_h, *p_h2, *p_aggH, *p_aggR, *p_inv;
    cudaGetSymbolAddress((void**)&p_h,    g_h);
    cudaGetSymbolAddress((void**)&p_h2,   g_h2);
    cudaGetSymbolAddress((void**)&p_aggH, g_aggH);
    cudaGetSymbolAddress((void**)&p_aggR, g_aggR);
    cudaGetSymbolAddress((void**)&p_inv,  g_inv);

    const int smemI = (KIN * DM + DM + 8 * KIN) * sizeof(float);              // ~87.5 KB
    const int smemN = (2 * DM * DM + RD * DM + 3 * DM + 8 * 288) * sizeof(float); // ~158 KB
    cudaFuncSetAttribute(k_input, cudaFuncAttributeMaxDynamicSharedMemorySize, smemI);
    cudaFuncSetAttribute(k_node,  cudaFuncAttributeMaxDynamicSharedMemorySize, smemN);

    // degree -> inv_deg
    k_zero<<<(NN + 255) / 256, 256>>>(p_inv, NN);
    k_deg<<<(EE + 255) / 256, 256>>>(eidx + EE);
    k_invdeg<<<(NN + 255) / 256, 256>>>();

    // input projection
    k_input<<<296, 256, smemI>>>(x, label, lemb, Win, bin, p_h);

    const float* hin = p_h;
    for (int l = 0; l < 2; l++) {
        float* hout = (l == 0) ? p_h2 : out;
        k_zero<<<8192, 256>>>(p_aggH, NN * DM);
        k_zero<<<2048, 256>>>(p_aggR, NN * RD);
        k_edge<<<EE / 8, 256>>>(eidx, eidx + EE, erel, hin, relemb + l * 1024 * RD);
        k_node<<<148, 256, smemN>>>(hin,
                                    Wself + l * DM * DM, Wn + l * DM * DM,
                                    Wr + l * RD * DM, bself + l * DM,
                                    lng + l * DM, lnb + l * DM, hout);
        hin = hout;
    }
}

// round 2
// speedup vs baseline: 1.6306x; 1.6306x over previous
#include <cuda_runtime.h>

#define NN 50000
#define EE 800000
#define DM 128
#define RD 32
#define KIN 160          // IN_DIM + LABEL_DIM
#define LN_EPS 1e-5f

// ---------------- scratch (device globals; no allocation allowed) -----------
__device__ float g_h[NN * DM];
__device__ float g_h2[NN * DM];
__device__ float g_aggH[NN * DM];
__device__ float g_aggR[NN * RD];
__device__ float g_inv[NN];

// ---------------- helpers ----------------------------------------------------
__device__ __forceinline__ void red_add_v4(float* addr, float4 v) {
    asm volatile("red.global.add.v4.f32 [%0], {%1,%2,%3,%4};"
                 :: "l"(addr), "f"(v.x), "f"(v.y), "f"(v.z), "f"(v.w)
                 : "memory");
}

__global__ void k_zero4(float4* __restrict__ p, int n4) {
    int i = blockIdx.x * blockDim.x + threadIdx.x;
    int stride = gridDim.x * blockDim.x;
    float4 z = make_float4(0.f, 0.f, 0.f, 0.f);
    for (; i < n4; i += stride) p[i] = z;
}

__global__ void k_deg(const int* __restrict__ dst) {
    int i = blockIdx.x * blockDim.x + threadIdx.x;
    if (i < EE) atomicAdd(&g_inv[dst[i]], 1.0f);
}

__global__ void k_invdeg() {
    int i = blockIdx.x * blockDim.x + threadIdx.x;
    if (i < NN) {
        float d = g_inv[i];
        g_inv[i] = d > 0.f ? (1.f / d) : 0.f;
    }
}

extern __shared__ float smdyn[];

// FMA of one weight vector into 4 row-accumulators
#define FMA4(S0, S1, S2, S3, WV)                                   \
    a0.x += (S0) * (WV).x; a0.y += (S0) * (WV).y;                  \
    a0.z += (S0) * (WV).z; a0.w += (S0) * (WV).w;                  \
    a1.x += (S1) * (WV).x; a1.y += (S1) * (WV).y;                  \
    a1.z += (S1) * (WV).z; a1.w += (S1) * (WV).w;                  \
    a2.x += (S2) * (WV).x; a2.y += (S2) * (WV).y;                  \
    a2.z += (S2) * (WV).z; a2.w += (S2) * (WV).w;                  \
    a3.x += (S3) * (WV).x; a3.y += (S3) * (WV).y;                  \
    a3.z += (S3) * (WV).z; a3.w += (S3) * (WV).w;

// GEMM segment: rows i0..i3 (SMEM), weights Wb (SMEM), LEN multiple of 4
#define SEG(Wb, OFF, LEN)                                              \
    _Pragma("unroll 8")                                                \
    for (int k = 0; k < (LEN); k += 4) {                               \
        float4 b0 = *(const float4*)(i0 + (OFF) + k);                  \
        float4 b1 = *(const float4*)(i1 + (OFF) + k);                  \
        float4 b2 = *(const float4*)(i2 + (OFF) + k);                  \
        float4 b3 = *(const float4*)(i3 + (OFF) + k);                  \
        { float4 wv = *(const float4*)((Wb) + (k + 0) * DM + c);       \
          FMA4(b0.x, b1.x, b2.x, b3.x, wv) }                           \
        { float4 wv = *(const float4*)((Wb) + (k + 1) * DM + c);       \
          FMA4(b0.y, b1.y, b2.y, b3.y, wv) }                           \
        { float4 wv = *(const float4*)((Wb) + (k + 2) * DM + c);       \
          FMA4(b0.z, b1.z, b2.z, b3.z, wv) }                           \
        { float4 wv = *(const float4*)((Wb) + (k + 3) * DM + c);       \
          FMA4(b0.w, b1.w, b2.w, b3.w, wv) }                           \
    }

// ---------------- input projection: h = relu([x, lemb[label]] @ W + b) ------
__global__ __launch_bounds__(256) void k_input(
    const float* __restrict__ x, const int* __restrict__ label,
    const float* __restrict__ lemb, const float* __restrict__ W,
    const float* __restrict__ b, float* __restrict__ hout)
{
    float* Ws  = smdyn;             // KIN*DM
    float* bs  = Ws + KIN * DM;     // DM
    float* ins = bs + DM;           // 8 warps * 4 rows * KIN
    int tid = threadIdx.x;

    for (int i = tid; i < (KIN * DM) / 4; i += 256)
        ((float4*)Ws)[i] = ((const float4*)W)[i];
    for (int i = tid; i < DM; i += 256) bs[i] = b[i];
    __syncthreads();

    int w = tid >> 5, lane = tid & 31;
    int c = lane * 4;
    const int ntiles = NN / 4;   // 12500, exact

    for (int tile = blockIdx.x * 8 + w; tile < ntiles; tile += gridDim.x * 8) {
        int v0 = tile * 4;
        float* in = ins + w * (4 * KIN);
        #pragma unroll
        for (int r = 0; r < 4; r++) {
            int v = v0 + r;
            float* inr = in + r * KIN;
            ((float4*)inr)[lane] = ((const float4*)(x + (size_t)v * DM))[lane];
            int lb = __ldg(&label[v]);
            inr[DM + lane] = lemb[lb * RD + lane];
        }
        __syncwarp();

        const float *i0 = in, *i1 = in + KIN, *i2 = in + 2 * KIN, *i3 = in + 3 * KIN;
        float4 a0 = *(float4*)(bs + c);
        float4 a1 = a0, a2 = a0, a3 = a0;
        SEG(Ws, 0, KIN)

        float4 accs[4] = {a0, a1, a2, a3};
        #pragma unroll
        for (int r = 0; r < 4; r++) {
            float4 o = accs[r];
            o.x = fmaxf(o.x, 0.f); o.y = fmaxf(o.y, 0.f);
            o.z = fmaxf(o.z, 0.f); o.w = fmaxf(o.w, 0.f);
            ((float4*)(hout + (size_t)(v0 + r) * DM))[lane] = o;
        }
    }
}

// ---------------- edge pass ---------------------------------------------------
__global__ __launch_bounds__(256) void k_edge(
    const int* __restrict__ src, const int* __restrict__ dst,
    const int* __restrict__ erel, const float* __restrict__ h,
    const float* __restrict__ rel)
{
    int warp = (blockIdx.x * blockDim.x + threadIdx.x) >> 5;
    int lane = threadIdx.x & 31;
    if (warp >= EE) return;

    int s = __ldg(&src[warp]);
    int d = __ldg(&dst[warp]);

    float4 hv = ((const float4*)(h + (size_t)s * DM))[lane];
    red_add_v4(&g_aggH[(size_t)d * DM + lane * 4], hv);

    if (lane < 8) {
        int r = __ldg(&erel[warp]);
        float4 rv = ((const float4*)(rel + (size_t)r * RD))[lane];
        red_add_v4(&g_aggR[(size_t)d * RD + lane * 4], rv);
    }
}

// ---------------- node pass: fused 3-GEMM + bias + relu + layernorm ----------
__global__ __launch_bounds__(256) void k_node(
    const float* __restrict__ hin,
    const float* __restrict__ Wself, const float* __restrict__ Wn,
    const float* __restrict__ Wr, const float* __restrict__ bias,
    const float* __restrict__ lng, const float* __restrict__ lnb,
    float* __restrict__ hout)
{
    float* Ws  = smdyn;                 // DM*DM
    float* Wns = Ws + DM * DM;          // DM*DM
    float* Wrs = Wns + DM * DM;         // RD*DM
    float* bs  = Wrs + RD * DM;         // DM
    float* gs  = bs + DM;               // DM
    float* lbs = gs + DM;               // DM
    float* ins = lbs + DM;              // 8 warps * 4 rows * 288

    int tid = threadIdx.x;
    for (int i = tid; i < (DM * DM) / 4; i += 256) {
        ((float4*)Ws)[i]  = ((const float4*)Wself)[i];
        ((float4*)Wns)[i] = ((const float4*)Wn)[i];
    }
    for (int i = tid; i < (RD * DM) / 4; i += 256)
        ((float4*)Wrs)[i] = ((const float4*)Wr)[i];
    for (int i = tid; i < DM; i += 256) {
        bs[i] = bias[i]; gs[i] = lng[i]; lbs[i] = lnb[i];
    }
    __syncthreads();

    int w = tid >> 5, lane = tid & 31;
    int c = lane * 4;
    const int ntiles = NN / 4;

    for (int tile = blockIdx.x * 8 + w; tile < ntiles; tile += gridDim.x * 8) {
        int v0 = tile * 4;
        float* in = ins + w * (4 * 288);
        #pragma unroll
        for (int r = 0; r < 4; r++) {
            int v = v0 + r;
            float iv = g_inv[v];
            float* inr = in + r * 288;
            ((float4*)inr)[lane] = ((const float4*)(hin + (size_t)v * DM))[lane];
            float4 av = ((const float4*)(g_aggH + (size_t)v * DM))[lane];
            av.x *= iv; av.y *= iv; av.z *= iv; av.w *= iv;
            ((float4*)(inr + DM))[lane] = av;
            if (lane < 8) {
                float4 rv = ((const float4*)(g_aggR + (size_t)v * RD))[lane];
                rv.x *= iv; rv.y *= iv; rv.z *= iv; rv.w *= iv;
                ((float4*)(inr + 2 * DM))[lane] = rv;
            }
        }
        __syncwarp();

        const float *i0 = in, *i1 = in + 288, *i2 = in + 576, *i3 = in + 864;
        float4 a0 = *(float4*)(bs + c);
        float4 a1 = a0, a2 = a0, a3 = a0;
        SEG(Ws,  0,       DM)
        SEG(Wns, DM,      DM)
        SEG(Wrs, 2 * DM,  RD)

        float4 accs[4] = {a0, a1, a2, a3};
        #pragma unroll
        for (int r = 0; r < 4; r++) {
            float4 o = accs[r];
            o.x = fmaxf(o.x, 0.f); o.y = fmaxf(o.y, 0.f);
            o.z = fmaxf(o.z, 0.f); o.w = fmaxf(o.w, 0.f);

            float s1 = o.x + o.y + o.z + o.w;
            float s2 = o.x * o.x + o.y * o.y + o.z * o.z + o.w * o.w;
            #pragma unroll
            for (int off = 16; off > 0; off >>= 1) {
                s1 += __shfl_xor_sync(0xffffffffu, s1, off);
                s2 += __shfl_xor_sync(0xffffffffu, s2, off);
            }
            float mu  = s1 * (1.f / 128.f);
            float var = s2 * (1.f / 128.f) - mu * mu;
            float rs  = rsqrtf(var + LN_EPS);

            float4 o4;
            o4.x = (o.x - mu) * rs * gs[c + 0] + lbs[c + 0];
            o4.y = (o.y - mu) * rs * gs[c + 1] + lbs[c + 1];
            o4.z = (o.z - mu) * rs * gs[c + 2] + lbs[c + 2];
            o4.w = (o.w - mu) * rs * gs[c + 3] + lbs[c + 3];
            ((float4*)(hout + (size_t)(v0 + r) * DM))[lane] = o4;
        }
    }
}

// ---------------- host launch -------------------------------------------------
extern "C" void kernel_launch(void* const* d_in, const int* in_sizes, int n_in,
                              void* d_out, int out_size)
{
    const float* x      = (const float*)d_in[0];
    const int*   label  = (const int*)d_in[1];
    const int*   eidx   = (const int*)d_in[2];
    const int*   erel   = (const int*)d_in[3];
    const float* lemb   = (const float*)d_in[4];
    const float* Win    = (const float*)d_in[5];
    const float* bin    = (const float*)d_in[6];
    const float* relemb = (const float*)d_in[7];
    const float* Wn     = (const float*)d_in[8];
    const float* Wself  = (const float*)d_in[9];
    const float* bself  = (const float*)d_in[10];
    const float* Wr     = (const float*)d_in[11];
    const float* lng    = (const float*)d_in[12];
    const float* lnb    = (const float*)d_in[13];
    float* out = (float*)d_out;

    float *p_h, *p_h2, *p_aggH, *p_aggR, *p_inv;
    cudaGetSymbolAddress((void**)&p_h,    g_h);
    cudaGetSymbolAddress((void**)&p_h2,   g_h2);
    cudaGetSymbolAddress((void**)&p_aggH, g_aggH);
    cudaGetSymbolAddress((void**)&p_aggR, g_aggR);
    cudaGetSymbolAddress((void**)&p_inv,  g_inv);

    const int smemI = (KIN * DM + DM + 8 * 4 * KIN) * sizeof(float);                  // ~101 KB
    const int smemN = (2 * DM * DM + RD * DM + 3 * DM + 8 * 4 * 288) * sizeof(float); // ~182 KB
    cudaFuncSetAttribute(k_input, cudaFuncAttributeMaxDynamicSharedMemorySize, smemI);
    cudaFuncSetAttribute(k_node,  cudaFuncAttributeMaxDynamicSharedMemorySize, smemN);

    // degree -> inv_deg
    k_zero4<<<64, 256>>>((float4*)p_inv, NN / 4);
    k_deg<<<(EE + 255) / 256, 256>>>(eidx + EE);
    k_invdeg<<<(NN + 255) / 256, 256>>>();

    // input projection
    k_input<<<148, 256, smemI>>>(x, label, lemb, Win, bin, p_h);

    const float* hin = p_h;
    for (int l = 0; l < 2; l++) {
        float* hout = (l == 0) ? p_h2 : out;
        k_zero4<<<2048, 256>>>((float4*)p_aggH, NN * DM / 4);
        k_zero4<<<512, 256>>>((float4*)p_aggR, NN * RD / 4);
        k_edge<<<EE / 8, 256>>>(eidx, eidx + EE, erel, hin, relemb + l * 1024 * RD);
        k_node<<<148, 256, smemN>>>(hin,
                                    Wself + l * DM * DM, Wn + l * DM * DM,
                                    Wr + l * RD * DM, bself + l * DM,
                                    lng + l * DM, lnb + l * DM, hout);
        hin = hout;
    }
}